// round 8
// baseline (speedup 1.0000x reference)
#include <cuda_runtime.h>

#define Bb 2
#define Nn 512
#define Ff 16
#define Dd 64
#define Hh 4
#define DhD 16
#define Cc 4
#define HIDD 256
#define NEGV (-9.0e15f)
#define MAXD 96
#define NB 128          // blocks: single wave on 148-SM chip
#define RPB 8           // rows per block (1024/128)

// global scratch (only what crosses blocks)
__device__ __align__(16) float g_k[Bb*Hh*Nn*DhD];
__device__ __align__(16) float g_v[Bb*Hh*Nn*DhD];
__device__ __align__(16) float g_bb[Bb*Nn*HIDD];  // y@W1[D:]
__device__ int g_cnt[Nn];
__device__ int g_js[Nn*MAXD];
__device__ unsigned g_count;
__device__ volatile unsigned g_gen;

__device__ __forceinline__ void gsync() {
    __threadfence();
    __syncthreads();
    if (threadIdx.x == 0) {
        const unsigned gen = g_gen;
        if (atomicInc(&g_count, NB - 1) == NB - 1) {
            g_gen = gen + 1;           // release: last block flips generation
        } else {
            while (g_gen == gen) { }   // spin (all blocks resident: safe)
        }
        __threadfence();
    }
    __syncthreads();
}

__global__ void __launch_bounds__(256, 1)
fused_all(const float* __restrict__ x,
          const float* __restrict__ adj,
          const float* __restrict__ W_emb,
          const float* __restrict__ Wq,
          const float* __restrict__ Wk,
          const float* __restrict__ Wv,
          const float* __restrict__ Wo,
          const float* __restrict__ W1,
          const float* __restrict__ b1,
          const float* __restrict__ W2,
          const float* __restrict__ b2,
          float* __restrict__ out) {
    __shared__ __align__(16) float xsh[RPB][Ff];
    __shared__ __align__(16) float hsh[RPB][Dd];
    __shared__ __align__(16) float qsh[RPB][Dd];
    __shared__ __align__(16) float psh[4][3][RPB][Dd];   // qkv partials
    __shared__ __align__(16) float osh[RPB][Dd];
    __shared__ __align__(16) float ysh[RPB][Dd];
    __shared__ __align__(16) float ash[RPB][HIDD];       // a = y@W1[:D]+b1

    const int t = threadIdx.x;
    const int warp = t >> 5, lane = t & 31;
    const int bid = blockIdx.x;
    const int row0 = bid * RPB;           // 8 consecutive global rows
    const int b = row0 >> 9;              // all 8 rows share b (512%8==0)
    const int n0 = row0 & (Nn - 1);

    // ================= PHASE A =================
    // adjacency preload (warps 0..3, row = bid*4 + warp), MLP first
    float adjv[16];
    const int arow_i = bid * 4 + warp;    // 0..511
    if (t < 128) {
        const float* arow = adj + arow_i * Nn;
#pragma unroll
        for (int s = 0; s < 16; s++) adjv[s] = arow[s * 32 + lane];
    }

    // stage x (8 rows x 16 feats)
    if (t < RPB * Ff) xsh[t >> 4][t & 15] = x[row0 * Ff + t];

    // NEG fill: 8 rows x 4 ch x 128 float4 = 4096 float4, 16/thread
    {
        const float4 neg4 = make_float4(NEGV, NEGV, NEGV, NEGV);
#pragma unroll
        for (int s = 0; s < 16; s++) {
            const int e = s * 256 + t;            // 0..4095
            const int r = e >> 9;
            const int rem = e & 511;
            const int ch = rem >> 7, col4 = rem & 127;
            float4* rp = (float4*)(out + (((size_t)(b * Cc + ch) * Nn + (n0 + r)) * Nn));
            rp[col4] = neg4;
        }
    }

    // adjacency ballot chain (register-resident)
    if (t < 128) {
        int base = 0;
#pragma unroll
        for (int s = 0; s < 16; s++) {
            const bool hit = (adjv[s] > 0.f);
            const unsigned bal = __ballot_sync(0xffffffffu, hit);
            if (hit) {
                const int pos = base + __popc(bal & ((1u << lane) - 1u));
                if (pos < MAXD) g_js[arow_i * MAXD + pos] = s * 32 + lane;
            }
            base += __popc(bal);
        }
        if (lane == 0) g_cnt[arow_i] = (base < MAXD) ? base : MAXD;
    }
    __syncthreads();

    // h = x @ W_emb : 512 items, 2/thread
#pragma unroll
    for (int s = 0; s < 2; s++) {
        const int e = s * 256 + t;
        const int r = e >> 6, c = e & 63;
        float acc = 0.f;
#pragma unroll
        for (int f = 0; f < Ff; f++)
            acc += xsh[r][f] * __ldg(W_emb + f * Dd + c);
        hsh[r][c] = acc;
    }
    __syncthreads();

    // qkv partials: thread=(c=t&63, seg=t>>6); seg covers 16 d's, 8 rows
    {
        const int c = t & 63, seg = t >> 6;
        float aq[RPB], ak[RPB], av[RPB];
#pragma unroll
        for (int r = 0; r < RPB; r++) { aq[r] = 0.f; ak[r] = 0.f; av[r] = 0.f; }
#pragma unroll
        for (int dd = 0; dd < 16; dd++) {
            const int d = seg * 16 + dd;
            const float wq = __ldg(Wq + d * Dd + c);
            const float wk = __ldg(Wk + d * Dd + c);
            const float wv = __ldg(Wv + d * Dd + c);
#pragma unroll
            for (int r = 0; r < RPB; r++) {
                const float hv = hsh[r][d];
                aq[r] += hv * wq; ak[r] += hv * wk; av[r] += hv * wv;
            }
        }
#pragma unroll
        for (int r = 0; r < RPB; r++) {
            psh[seg][0][r][c] = aq[r];
            psh[seg][1][r][c] = ak[r];
            psh[seg][2][r][c] = av[r];
        }
    }
    __syncthreads();

    // reduce 4 segs: 1536 outputs, 6/thread. q->smem, k/v->global
#pragma unroll
    for (int s = 0; s < 6; s++) {
        const int idx = s * 256 + t;
        const int m = idx >> 9;           // 0=q,1=k,2=v
        const int rem = idx & 511;
        const int r = rem >> 6, c = rem & 63;
        const float v = psh[0][m][r][c] + psh[1][m][r][c]
                      + psh[2][m][r][c] + psh[3][m][r][c];
        if (m == 0) {
            qsh[r][c] = v;
        } else {
            const int hd = c >> 4, dh = c & 15;
            const int gi = ((b * Hh + hd) * Nn + (n0 + r)) * DhD + dh;
            if (m == 1) g_k[gi] = v; else g_v[gi] = v;
        }
    }

    gsync();

    // ================= PHASE B =================
    // attention: warp = local row r; loop heads
    {
        const int r = warp;
        const int i = n0 + r;
        const int cnt = g_cnt[i];
        const int* js = g_js + i * MAXD;
        const int nch = (cnt + 31) >> 5;

        for (int hd = 0; hd < Hh; hd++) {
            float qr[DhD];
#pragma unroll
            for (int d = 0; d < DhD; d++) qr[d] = qsh[r][hd * DhD + d];

            const float* kbase = g_k + (b * Hh + hd) * Nn * DhD;
            const float* vbase = g_v + (b * Hh + hd) * Nn * DhD;

            float sc[3];
            int jj[3];
            float m = -3.0e38f;
#pragma unroll
            for (int c = 0; c < 3; c++) {
                sc[c] = -3.0e38f; jj[c] = 0;
                if (c < nch) {
                    const int e = c * 32 + lane;
                    if (e < cnt) {
                        const int j = js[e];
                        jj[c] = j;
                        const float* kr = kbase + j * DhD;
                        float dot = 0.f;
#pragma unroll
                        for (int d = 0; d < DhD; d++) dot += qr[d] * kr[d];
                        sc[c] = dot * 0.25f;
                    }
                    m = fmaxf(m, sc[c]);
                }
            }
#pragma unroll
            for (int o = 16; o > 0; o >>= 1)
                m = fmaxf(m, __shfl_xor_sync(0xffffffffu, m, o));

            float sum = 0.f;
#pragma unroll
            for (int c = 0; c < 3; c++) {
                sc[c] = expf(sc[c] - m);
                sum += sc[c];
            }
#pragma unroll
            for (int o = 16; o > 0; o >>= 1)
                sum += __shfl_xor_sync(0xffffffffu, sum, o);

            float ov[DhD];
#pragma unroll
            for (int d = 0; d < DhD; d++) ov[d] = 0.f;
#pragma unroll
            for (int c = 0; c < 3; c++) {
                if (c < nch && sc[c] > 0.f) {
                    const float* vr = vbase + jj[c] * DhD;
                    const float e = sc[c];
#pragma unroll
                    for (int d = 0; d < DhD; d++) ov[d] += e * vr[d];
                }
            }
#pragma unroll
            for (int d = 0; d < DhD; d++) {
#pragma unroll
                for (int o = 16; o > 0; o >>= 1)
                    ov[d] += __shfl_xor_sync(0xffffffffu, ov[d], o);
            }
            if (lane == 0) {
                const float inv = 1.f / sum;
#pragma unroll
                for (int d = 0; d < DhD; d++) osh[r][hd * DhD + d] = ov[d] * inv;
            }
        }
    }
    __syncthreads();

    // y = h + o @ Wo : 512 items, 2/thread
#pragma unroll
    for (int s = 0; s < 2; s++) {
        const int e = s * 256 + t;
        const int r = e >> 6, c = e & 63;
        float acc = hsh[r][c];
#pragma unroll 8
        for (int d = 0; d < Dd; d++)
            acc += osh[r][d] * __ldg(Wo + d * Dd + c);
        ysh[r][c] = acc;
    }
    __syncthreads();

    // a/b: thread = column c (256), 8 rows, d-loop
    {
        const int c = t;
        const float bias = __ldg(b1 + c);
        float fa[RPB], fb[RPB];
#pragma unroll
        for (int r = 0; r < RPB; r++) { fa[r] = 0.f; fb[r] = 0.f; }
#pragma unroll 8
        for (int d = 0; d < Dd; d++) {
            const float wa = __ldg(W1 + d * HIDD + c);
            const float wb = __ldg(W1 + (Dd + d) * HIDD + c);
#pragma unroll
            for (int r = 0; r < RPB; r++) {
                const float yv = ysh[r][d];
                fa[r] += yv * wa;
                fb[r] += yv * wb;
            }
        }
#pragma unroll
        for (int r = 0; r < RPB; r++) {
            ash[r][c] = fa[r] + bias;
            g_bb[(row0 + r) * HIDD + c] = fb[r];
        }
    }

    gsync();

    // ================= PHASE C: scatter =================
    {
        const int r = warp;                 // warp per row
        const int i = n0 + r;
        const int cnt = g_cnt[i];
        const int* js = g_js + i * MAXD;
        const int h0 = lane * 8;

        const float4 a0 = *(const float4*)&ash[r][h0];
        const float4 a1 = *(const float4*)&ash[r][h0 + 4];
        float4 w[8];
#pragma unroll
        for (int k = 0; k < 8; k++) w[k] = __ldg((const float4*)W2 + h0 + k);
        const float b20 = __ldg(b2 + 0), b21 = __ldg(b2 + 1);
        const float b22 = __ldg(b2 + 2), b23 = __ldg(b2 + 3);

        for (int e = 0; e < cnt; e++) {
            const int j = js[e];
            const float4* bp = (const float4*)(g_bb + ((size_t)(b * Nn + j)) * HIDD + h0);
            const float4 bv0 = bp[0], bv1 = bp[1];

            float acc0 = 0.f, acc1 = 0.f, acc2 = 0.f, acc3 = 0.f;
            float tt;
#define RELU_FMA(AV, BV, WK) \
            tt = fmaxf((AV) + (BV), 0.f); \
            acc0 += tt * (WK).x; acc1 += tt * (WK).y; acc2 += tt * (WK).z; acc3 += tt * (WK).w;
            RELU_FMA(a0.x, bv0.x, w[0]);
            RELU_FMA(a0.y, bv0.y, w[1]);
            RELU_FMA(a0.z, bv0.z, w[2]);
            RELU_FMA(a0.w, bv0.w, w[3]);
            RELU_FMA(a1.x, bv1.x, w[4]);
            RELU_FMA(a1.y, bv1.y, w[5]);
            RELU_FMA(a1.z, bv1.z, w[6]);
            RELU_FMA(a1.w, bv1.w, w[7]);
#undef RELU_FMA

#pragma unroll
            for (int o = 16; o > 0; o >>= 1) {
                acc0 += __shfl_xor_sync(0xffffffffu, acc0, o);
                acc1 += __shfl_xor_sync(0xffffffffu, acc1, o);
                acc2 += __shfl_xor_sync(0xffffffffu, acc2, o);
                acc3 += __shfl_xor_sync(0xffffffffu, acc3, o);
            }
            if (lane == 0) {
                out[(((size_t)(b * Cc + 0) * Nn + i) * Nn) + j] = acc0 + b20;
                out[(((size_t)(b * Cc + 1) * Nn + i) * Nn) + j] = acc1 + b21;
                out[(((size_t)(b * Cc + 2) * Nn + i) * Nn) + j] = acc2 + b22;
                out[(((size_t)(b * Cc + 3) * Nn + i) * Nn) + j] = acc3 + b23;
            }
        }
    }
}

// ---------------------------------------------------------------------------
extern "C" void kernel_launch(void* const* d_in, const int* in_sizes, int n_in,
                              void* d_out, int out_size) {
    const float* x     = (const float*)d_in[0];
    const float* adj   = (const float*)d_in[1];
    const float* W_emb = (const float*)d_in[2];
    const float* Wq    = (const float*)d_in[3];
    const float* Wk    = (const float*)d_in[4];
    const float* Wv    = (const float*)d_in[5];
    const float* Wo    = (const float*)d_in[6];
    const float* W1    = (const float*)d_in[7];
    const float* b1    = (const float*)d_in[8];
    const float* W2    = (const float*)d_in[9];
    const float* b2    = (const float*)d_in[10];
    float* out = (float*)d_out;

    fused_all<<<NB, 256>>>(x, adj, W_emb, Wq, Wk, Wv, Wo, W1, b1, W2, b2, out);
}

// round 9
// speedup vs baseline: 1.0693x; 1.0693x over previous
#include <cuda_runtime.h>

#define Bb 2
#define Nn 512
#define Ff 16
#define Dd 64
#define Hh 4
#define DhD 16
#define Cc 4
#define HIDD 256
#define NEGV (-9.0e15f)
#define MAXD 96
#define NB 128          // blocks: single wave (<=148 SMs)
#define RPB 8           // rows per block

// global scratch (only what crosses blocks)
__device__ __align__(16) float g_k[Bb*Hh*Nn*DhD];
__device__ __align__(16) float g_v[Bb*Hh*Nn*DhD];
__device__ __align__(16) float g_bb[Bb*Nn*HIDD];  // y@W1[D:]
__device__ int g_cnt[Nn];
__device__ int g_js[Nn*MAXD];
__device__ unsigned g_count;
__device__ volatile unsigned g_gen;

__device__ __forceinline__ void gsync() {
    __threadfence();
    __syncthreads();
    if (threadIdx.x == 0) {
        const unsigned gen = g_gen;
        if (atomicInc(&g_count, NB - 1) == NB - 1) {
            g_gen = gen + 1;
        } else {
            while (g_gen == gen) { }
        }
        __threadfence();
    }
    __syncthreads();
}

__global__ void __launch_bounds__(1024, 1)
fused_all(const float* __restrict__ x,
          const float* __restrict__ adj,
          const float* __restrict__ W_emb,
          const float* __restrict__ Wq,
          const float* __restrict__ Wk,
          const float* __restrict__ Wv,
          const float* __restrict__ Wo,
          const float* __restrict__ W1,
          const float* __restrict__ b1,
          const float* __restrict__ W2,
          const float* __restrict__ b2,
          float* __restrict__ out) {
    __shared__ __align__(16) float xsh[RPB][Ff];
    __shared__ __align__(16) float hsh[RPB][Dd];
    __shared__ __align__(16) float qsh[RPB][Dd];
    __shared__ __align__(16) float psh[4][3][RPB][Dd];   // qkv partials (24KB)
    __shared__ __align__(16) float osh[RPB][Dd];
    __shared__ __align__(16) float ysh[RPB][Dd];
    __shared__ __align__(16) float pshy[2][RPB][Dd];     // y partials (4KB)
    __shared__ __align__(16) float ash[RPB][HIDD];       // a (8KB)

    const int t = threadIdx.x;
    const int warp = t >> 5, lane = t & 31;
    const int bid = blockIdx.x;
    const int row0 = bid * RPB;
    const int b = row0 >> 9;
    const int n0 = row0 & (Nn - 1);

    // ================= PHASE A =================
    // adjacency preload (warps 0..3, row = bid*4 + warp), MLP-first
    float adjv[16];
    const int arow_i = bid * 4 + warp;    // 0..511
    if (t < 128) {
        const float* arow = adj + arow_i * Nn;
#pragma unroll
        for (int s = 0; s < 16; s++) adjv[s] = arow[s * 32 + lane];
    }

    // stage x
    if (t < RPB * Ff) xsh[t >> 4][t & 15] = x[row0 * Ff + t];

    // NEG fill: 4096 float4, 4 per thread
    {
        const float4 neg4 = make_float4(NEGV, NEGV, NEGV, NEGV);
#pragma unroll
        for (int s = 0; s < 4; s++) {
            const int e = s * 1024 + t;           // 0..4095
            const int r = e >> 9;
            const int rem = e & 511;
            const int ch = rem >> 7, col4 = rem & 127;
            float4* rp = (float4*)(out + (((size_t)(b * Cc + ch) * Nn + (n0 + r)) * Nn));
            rp[col4] = neg4;
        }
    }

    // adjacency ballot chain
    if (t < 128) {
        int base = 0;
#pragma unroll
        for (int s = 0; s < 16; s++) {
            const bool hit = (adjv[s] > 0.f);
            const unsigned bal = __ballot_sync(0xffffffffu, hit);
            if (hit) {
                const int pos = base + __popc(bal & ((1u << lane) - 1u));
                if (pos < MAXD) g_js[arow_i * MAXD + pos] = s * 32 + lane;
            }
            base += __popc(bal);
        }
        if (lane == 0) g_cnt[arow_i] = (base < MAXD) ? base : MAXD;
    }
    __syncthreads();

    // h = x @ W_emb : threads 0..511, thread=(r,c)
    if (t < RPB * Dd) {
        const int r = t >> 6, c = t & 63;
        float acc = 0.f;
#pragma unroll
        for (int f = 0; f < Ff; f++)
            acc += xsh[r][f] * __ldg(W_emb + f * Dd + c);
        hsh[r][c] = acc;
    }
    __syncthreads();

    // qkv partials: thread = (c:64, seg:4, rpair:4); 16 d's, 2 rows
    {
        const int c = t & 63;
        const int seg = (t >> 6) & 3;
        const int rp = t >> 8;               // 0..3
        const int rA = rp * 2, rB = rp * 2 + 1;
        float aq0 = 0.f, aq1 = 0.f, ak0 = 0.f, ak1 = 0.f, av0 = 0.f, av1 = 0.f;
#pragma unroll
        for (int dd = 0; dd < 16; dd++) {
            const int d = seg * 16 + dd;
            const float wq = __ldg(Wq + d * Dd + c);
            const float wk = __ldg(Wk + d * Dd + c);
            const float wv = __ldg(Wv + d * Dd + c);
            const float hA = hsh[rA][d], hB = hsh[rB][d];
            aq0 += hA * wq; aq1 += hB * wq;
            ak0 += hA * wk; ak1 += hB * wk;
            av0 += hA * wv; av1 += hB * wv;
        }
        psh[seg][0][rA][c] = aq0; psh[seg][0][rB][c] = aq1;
        psh[seg][1][rA][c] = ak0; psh[seg][1][rB][c] = ak1;
        psh[seg][2][rA][c] = av0; psh[seg][2][rB][c] = av1;
    }
    __syncthreads();

    // reduce 4 segs: 1536 outputs; q->smem, k/v->global
#pragma unroll
    for (int s = 0; s < 2; s++) {
        const int idx = s * 1024 + t;
        if (idx < 3 * RPB * Dd) {
            const int m = idx >> 9;           // 0=q,1=k,2=v
            const int rem = idx & 511;
            const int r = rem >> 6, c = rem & 63;
            const float v = psh[0][m][r][c] + psh[1][m][r][c]
                          + psh[2][m][r][c] + psh[3][m][r][c];
            if (m == 0) {
                qsh[r][c] = v;
            } else {
                const int hd = c >> 4, dh = c & 15;
                const int gi = ((b * Hh + hd) * Nn + (n0 + r)) * DhD + dh;
                if (m == 1) g_k[gi] = v; else g_v[gi] = v;
            }
        }
    }

    gsync();

    // ================= PHASE B =================
    // attention: 32 warps = (r = warp&7, hd = warp>>3)
    {
        const int r = warp & 7;
        const int hd = warp >> 3;
        const int i = n0 + r;
        const int cnt = g_cnt[i];
        const int* js = g_js + i * MAXD;
        const int nch = (cnt + 31) >> 5;

        float qr[DhD];
#pragma unroll
        for (int d = 0; d < DhD; d++) qr[d] = qsh[r][hd * DhD + d];

        const float* kbase = g_k + (b * Hh + hd) * Nn * DhD;
        const float* vbase = g_v + (b * Hh + hd) * Nn * DhD;

        float sc[3];
        int jj[3];
        float m = -3.0e38f;
#pragma unroll
        for (int c = 0; c < 3; c++) {
            sc[c] = -3.0e38f; jj[c] = 0;
            if (c < nch) {
                const int e = c * 32 + lane;
                if (e < cnt) {
                    const int j = js[e];
                    jj[c] = j;
                    const float* kr = kbase + j * DhD;
                    float dot = 0.f;
#pragma unroll
                    for (int d = 0; d < DhD; d++) dot += qr[d] * kr[d];
                    sc[c] = dot * 0.25f;
                }
                m = fmaxf(m, sc[c]);
            }
        }
#pragma unroll
        for (int o = 16; o > 0; o >>= 1)
            m = fmaxf(m, __shfl_xor_sync(0xffffffffu, m, o));

        float sum = 0.f;
#pragma unroll
        for (int c = 0; c < 3; c++) {
            sc[c] = expf(sc[c] - m);
            sum += sc[c];
        }
#pragma unroll
        for (int o = 16; o > 0; o >>= 1)
            sum += __shfl_xor_sync(0xffffffffu, sum, o);

        float ov[DhD];
#pragma unroll
        for (int d = 0; d < DhD; d++) ov[d] = 0.f;
#pragma unroll
        for (int c = 0; c < 3; c++) {
            if (c < nch && sc[c] > 0.f) {
                const float* vr = vbase + jj[c] * DhD;
                const float e = sc[c];
#pragma unroll
                for (int d = 0; d < DhD; d++) ov[d] += e * vr[d];
            }
        }
#pragma unroll
        for (int d = 0; d < DhD; d++) {
#pragma unroll
            for (int o = 16; o > 0; o >>= 1)
                ov[d] += __shfl_xor_sync(0xffffffffu, ov[d], o);
        }
        if (lane == 0) {
            const float inv = 1.f / sum;
#pragma unroll
            for (int d = 0; d < DhD; d++) osh[r][hd * DhD + d] = ov[d] * inv;
        }
    }
    __syncthreads();

    // y partials: thread=(r,c,half): chain 32
    {
        const int c = t & 63;
        const int r = (t >> 6) & 7;
        const int half = t >> 9;
        float acc = 0.f;
#pragma unroll
        for (int dd = 0; dd < 32; dd++) {
            const int d = half * 32 + dd;
            acc += osh[r][d] * __ldg(Wo + d * Dd + c);
        }
        pshy[half][r][c] = acc;
    }
    __syncthreads();

    if (t < RPB * Dd) {
        const int r = t >> 6, c = t & 63;
        ysh[r][c] = hsh[r][c] + pshy[0][r][c] + pshy[1][r][c];
    }
    __syncthreads();

    // a/b: thread = (c:256, rpair:4): 2 rows each
    {
        const int c = t & 255;
        const int rp = t >> 8;
        const int rA = rp * 2, rB = rp * 2 + 1;
        const float bias = __ldg(b1 + c);
        float faA = 0.f, faB = 0.f, fbA = 0.f, fbB = 0.f;
#pragma unroll 8
        for (int d = 0; d < Dd; d++) {
            const float wa = __ldg(W1 + d * HIDD + c);
            const float wb = __ldg(W1 + (Dd + d) * HIDD + c);
            const float yA = ysh[rA][d], yB = ysh[rB][d];
            faA += yA * wa; faB += yB * wa;
            fbA += yA * wb; fbB += yB * wb;
        }
        ash[rA][c] = faA + bias;
        ash[rB][c] = faB + bias;
        g_bb[(row0 + rA) * HIDD + c] = fbA;
        g_bb[(row0 + rB) * HIDD + c] = fbB;
    }

    gsync();

    // ================= PHASE C: scatter =================
    // 32 warps = (r = warp&7, estride = warp>>3): entries e = estride, +4
    {
        const int r = warp & 7;
        const int es = warp >> 3;
        const int i = n0 + r;
        const int cnt = g_cnt[i];
        const int* js = g_js + i * MAXD;
        const int h0 = lane * 8;

        const float4 a0 = *(const float4*)&ash[r][h0];
        const float4 a1 = *(const float4*)&ash[r][h0 + 4];
        float4 w[8];
#pragma unroll
        for (int k = 0; k < 8; k++) w[k] = __ldg((const float4*)W2 + h0 + k);
        const float b20 = __ldg(b2 + 0), b21 = __ldg(b2 + 1);
        const float b22 = __ldg(b2 + 2), b23 = __ldg(b2 + 3);

        for (int e = es; e < cnt; e += 4) {
            const int j = js[e];
            const float4* bp = (const float4*)(g_bb + ((size_t)(b * Nn + j)) * HIDD + h0);
            const float4 bv0 = bp[0], bv1 = bp[1];

            float acc0 = 0.f, acc1 = 0.f, acc2 = 0.f, acc3 = 0.f;
            float tt;
#define RELU_FMA(AV, BV, WK) \
            tt = fmaxf((AV) + (BV), 0.f); \
            acc0 += tt * (WK).x; acc1 += tt * (WK).y; acc2 += tt * (WK).z; acc3 += tt * (WK).w;
            RELU_FMA(a0.x, bv0.x, w[0]);
            RELU_FMA(a0.y, bv0.y, w[1]);
            RELU_FMA(a0.z, bv0.z, w[2]);
            RELU_FMA(a0.w, bv0.w, w[3]);
            RELU_FMA(a1.x, bv1.x, w[4]);
            RELU_FMA(a1.y, bv1.y, w[5]);
            RELU_FMA(a1.z, bv1.z, w[6]);
            RELU_FMA(a1.w, bv1.w, w[7]);
#undef RELU_FMA

#pragma unroll
            for (int o = 16; o > 0; o >>= 1) {
                acc0 += __shfl_xor_sync(0xffffffffu, acc0, o);
                acc1 += __shfl_xor_sync(0xffffffffu, acc1, o);
                acc2 += __shfl_xor_sync(0xffffffffu, acc2, o);
                acc3 += __shfl_xor_sync(0xffffffffu, acc3, o);
            }
            if (lane == 0) {
                out[(((size_t)(b * Cc + 0) * Nn + i) * Nn) + j] = acc0 + b20;
                out[(((size_t)(b * Cc + 1) * Nn + i) * Nn) + j] = acc1 + b21;
                out[(((size_t)(b * Cc + 2) * Nn + i) * Nn) + j] = acc2 + b22;
                out[(((size_t)(b * Cc + 3) * Nn + i) * Nn) + j] = acc3 + b23;
            }
        }
    }
}

// ---------------------------------------------------------------------------
extern "C" void kernel_launch(void* const* d_in, const int* in_sizes, int n_in,
                              void* d_out, int out_size) {
    const float* x     = (const float*)d_in[0];
    const float* adj   = (const float*)d_in[1];
    const float* W_emb = (const float*)d_in[2];
    const float* Wq    = (const float*)d_in[3];
    const float* Wk    = (const float*)d_in[4];
    const float* Wv    = (const float*)d_in[5];
    const float* Wo    = (const float*)d_in[6];
    const float* W1    = (const float*)d_in[7];
    const float* b1    = (const float*)d_in[8];
    const float* W2    = (const float*)d_in[9];
    const float* b2    = (const float*)d_in[10];
    float* out = (float*)d_out;

    fused_all<<<NB, 1024>>>(x, adj, W_emb, Wq, Wk, Wv, Wo, W1, b1, W2, b2, out);
}

// round 10
// speedup vs baseline: 1.1395x; 1.0656x over previous
#include <cuda_runtime.h>

#define Bb 2
#define Nn 512
#define Ff 16
#define Dd 64
#define Hh 4
#define DhD 16
#define Cc 4
#define HIDD 256
#define NEGV (-9.0e15f)
#define MAXD 96
#define NB 128          // blocks: single wave (<=148 SMs)
#define RPB 8           // rows per block

// global scratch
__device__ __align__(16) float g_k[Bb*Hh*Nn*DhD];
__device__ __align__(16) float g_v[Bb*Hh*Nn*DhD];
__device__ __align__(16) float g_bb[Bb*Nn*HIDD];
__device__ int g_cnt[Nn];
__device__ int g_js[Nn*MAXD];
__device__ unsigned g_count;
__device__ volatile unsigned g_gen;

__device__ __forceinline__ void gsync() {
    __threadfence();
    __syncthreads();
    if (threadIdx.x == 0) {
        const unsigned gen = g_gen;
        if (atomicInc(&g_count, NB - 1) == NB - 1) {
            g_gen = gen + 1;
        } else {
            while (g_gen == gen) { }
        }
        __threadfence();
    }
    __syncthreads();
}

__global__ void __launch_bounds__(1024, 1)
fused_all(const float* __restrict__ x,
          const float* __restrict__ adj,
          const float* __restrict__ W_emb,
          const float* __restrict__ Wq,
          const float* __restrict__ Wk,
          const float* __restrict__ Wv,
          const float* __restrict__ Wo,
          const float* __restrict__ W1,
          const float* __restrict__ b1,
          const float* __restrict__ W2,
          const float* __restrict__ b2,
          float* __restrict__ out) {
    // overlaid arena: phase A = qkv partials (24KB); phase B = wsh(12KB)+jsh(3KB)
    __shared__ __align__(16) char arena[24576];
    __shared__ __align__(16) float xsh[RPB][Ff];     // 0.5KB
    __shared__ __align__(16) float hsh[RPB][Dd];     // 2KB
    __shared__ __align__(16) float qsh[RPB][Dd];     // 2KB
    __shared__ __align__(16) float osh[RPB][Dd];     // 2KB
    __shared__ __align__(16) float ysh[RPB][Dd];     // 2KB
    __shared__ __align__(16) float pshy[2][RPB][Dd]; // 4KB
    __shared__ __align__(16) float ash[RPB][HIDD];   // 8KB
    __shared__ int csh[RPB];

    float (*psh)[3][RPB][Dd] = (float (*)[3][RPB][Dd])arena;        // [4][3][8][64]
    float (*wsh)[Hh][MAXD]   = (float (*)[Hh][MAXD])arena;          // [8][4][96] 12KB
    int   (*jsh)[MAXD]       = (int (*)[MAXD])(arena + 12288 + 2048); // [8][96] 3KB

    const int t = threadIdx.x;
    const int warp = t >> 5, lane = t & 31;
    const int bid = blockIdx.x;
    const int row0 = bid * RPB;
    const int b = row0 >> 9;
    const int n0 = row0 & (Nn - 1);

    // ================= PHASE A =================
    // adjacency: preload (MLP=16) then IMMEDIATE ballot chain (short live range)
    if (t < 128) {
        const int arow_i = bid * 4 + warp;    // 0..511
        const float* arow = adj + arow_i * Nn;
        float adjv[16];
#pragma unroll
        for (int s = 0; s < 16; s++) adjv[s] = arow[s * 32 + lane];
        int base = 0;
#pragma unroll
        for (int s = 0; s < 16; s++) {
            const bool hit = (adjv[s] > 0.f);
            const unsigned bal = __ballot_sync(0xffffffffu, hit);
            if (hit) {
                const int pos = base + __popc(bal & ((1u << lane) - 1u));
                if (pos < MAXD) g_js[arow_i * MAXD + pos] = s * 32 + lane;
            }
            base += __popc(bal);
        }
        if (lane == 0) g_cnt[arow_i] = (base < MAXD) ? base : MAXD;
    }

    // stage x
    if (t >= 128 && t < 128 + RPB * Ff) {
        const int e = t - 128;
        xsh[e >> 4][e & 15] = x[row0 * Ff + e];
    }

    // NEG fill: 4096 float4, 4/thread
    {
        const float4 neg4 = make_float4(NEGV, NEGV, NEGV, NEGV);
#pragma unroll
        for (int s = 0; s < 4; s++) {
            const int e = s * 1024 + t;
            const int r = e >> 9;
            const int rem = e & 511;
            const int ch = rem >> 7, col4 = rem & 127;
            float4* rp = (float4*)(out + (((size_t)(b * Cc + ch) * Nn + (n0 + r)) * Nn));
            rp[col4] = neg4;
        }
    }
    __syncthreads();

    // h = x @ W_emb : threads 0..511
    if (t < RPB * Dd) {
        const int r = t >> 6, c = t & 63;
        float acc = 0.f;
#pragma unroll
        for (int f = 0; f < Ff; f++)
            acc += xsh[r][f] * __ldg(W_emb + f * Dd + c);
        hsh[r][c] = acc;
    }
    __syncthreads();

    // qkv partials: thread = (c:64, seg:4, rpair:4); 16 d's, 2 rows
    {
        const int c = t & 63;
        const int seg = (t >> 6) & 3;
        const int rp = t >> 8;
        const int rA = rp * 2, rB = rp * 2 + 1;
        float aq0 = 0.f, aq1 = 0.f, ak0 = 0.f, ak1 = 0.f, av0 = 0.f, av1 = 0.f;
#pragma unroll
        for (int dd = 0; dd < 16; dd++) {
            const int d = seg * 16 + dd;
            const float wq = __ldg(Wq + d * Dd + c);
            const float wk = __ldg(Wk + d * Dd + c);
            const float wv = __ldg(Wv + d * Dd + c);
            const float hA = hsh[rA][d], hB = hsh[rB][d];
            aq0 += hA * wq; aq1 += hB * wq;
            ak0 += hA * wk; ak1 += hB * wk;
            av0 += hA * wv; av1 += hB * wv;
        }
        psh[seg][0][rA][c] = aq0; psh[seg][0][rB][c] = aq1;
        psh[seg][1][rA][c] = ak0; psh[seg][1][rB][c] = ak1;
        psh[seg][2][rA][c] = av0; psh[seg][2][rB][c] = av1;
    }
    __syncthreads();

    // reduce: q->smem, k/v->global
#pragma unroll
    for (int s = 0; s < 2; s++) {
        const int idx = s * 1024 + t;
        if (idx < 3 * RPB * Dd) {
            const int m = idx >> 9;
            const int rem = idx & 511;
            const int r = rem >> 6, c = rem & 63;
            const float v = psh[0][m][r][c] + psh[1][m][r][c]
                          + psh[2][m][r][c] + psh[3][m][r][c];
            if (m == 0) {
                qsh[r][c] = v;
            } else {
                const int hd = c >> 4, dh = c & 15;
                const int gi = ((b * Hh + hd) * Nn + (n0 + r)) * DhD + dh;
                if (m == 1) g_k[gi] = v; else g_v[gi] = v;
            }
        }
    }

    gsync();   // also fences arena reuse

    // ================= PHASE B =================
    // stage neighbor lists into smem
    if (warp < RPB) {
        const int r = warp;
        const int i = n0 + r;
        const int cnt = g_cnt[i];
        if (lane == 0) csh[r] = cnt;
        for (int e = lane; e < cnt; e += 32) jsh[r][e] = g_js[i * MAXD + e];
    }
    __syncthreads();

    // stage 1: softmax weights per (r, hd) -> wsh
    {
        const int r = warp & 7;
        const int hd = warp >> 3;
        const int cnt = csh[r];
        const int nch = (cnt + 31) >> 5;

        const float4* qp = (const float4*)&qsh[r][hd * DhD];
        const float4 q0 = qp[0], q1 = qp[1], q2 = qp[2], q3 = qp[3];
        const float* kbase = g_k + (b * Hh + hd) * Nn * DhD;

        float sc[3];
        float m = -3.0e38f;
#pragma unroll
        for (int c = 0; c < 3; c++) {
            sc[c] = -3.0e38f;
            if (c < nch) {
                const int e = c * 32 + lane;
                if (e < cnt) {
                    const int j = jsh[r][e];
                    const float4* kp = (const float4*)(kbase + j * DhD);
                    const float4 k0 = kp[0], k1 = kp[1], k2 = kp[2], k3 = kp[3];
                    float dot = q0.x*k0.x + q0.y*k0.y + q0.z*k0.z + q0.w*k0.w;
                    dot += q1.x*k1.x + q1.y*k1.y + q1.z*k1.z + q1.w*k1.w;
                    dot += q2.x*k2.x + q2.y*k2.y + q2.z*k2.z + q2.w*k2.w;
                    dot += q3.x*k3.x + q3.y*k3.y + q3.z*k3.z + q3.w*k3.w;
                    sc[c] = dot * 0.25f;
                }
                m = fmaxf(m, sc[c]);
            }
        }
#pragma unroll
        for (int o = 16; o > 0; o >>= 1)
            m = fmaxf(m, __shfl_xor_sync(0xffffffffu, m, o));

        float sum = 0.f;
#pragma unroll
        for (int c = 0; c < 3; c++) {
            sc[c] = expf(sc[c] - m);
            sum += sc[c];
        }
#pragma unroll
        for (int o = 16; o > 0; o >>= 1)
            sum += __shfl_xor_sync(0xffffffffu, sum, o);
        const float inv = 1.f / sum;

#pragma unroll
        for (int c = 0; c < 3; c++) {
            if (c < nch) {
                const int e = c * 32 + lane;
                if (e < cnt) wsh[r][hd][e] = sc[c] * inv;
            }
        }
    }
    __syncthreads();

    // stage 2: o[r][hd][d] = sum_e w * v  — one register accumulator/thread
    if (t < RPB * Hh * DhD) {
        const int r = t >> 6;
        const int hd = (t >> 4) & 3;
        const int d = t & 15;
        const int cnt = csh[r];
        const float* vbase = g_v + (b * Hh + hd) * Nn * DhD + d;
        const float* wrow = wsh[r][hd];
        const int* jrow = jsh[r];

        float ov = 0.f;
        int e = 0;
        for (; e + 4 <= cnt; e += 4) {
            const int j0 = jrow[e], j1 = jrow[e+1], j2 = jrow[e+2], j3 = jrow[e+3];
            const float v0 = vbase[j0 * DhD], v1 = vbase[j1 * DhD];
            const float v2 = vbase[j2 * DhD], v3 = vbase[j3 * DhD];
            ov += wrow[e] * v0;
            ov += wrow[e+1] * v1;
            ov += wrow[e+2] * v2;
            ov += wrow[e+3] * v3;
        }
        for (; e < cnt; e++)
            ov += wrow[e] * vbase[jrow[e] * DhD];
        osh[r][hd * DhD + d] = ov;
    }
    __syncthreads();

    // y partials
    {
        const int c = t & 63;
        const int r = (t >> 6) & 7;
        const int half = t >> 9;
        float acc = 0.f;
#pragma unroll
        for (int dd = 0; dd < 32; dd++) {
            const int d = half * 32 + dd;
            acc += osh[r][d] * __ldg(Wo + d * Dd + c);
        }
        pshy[half][r][c] = acc;
    }
    __syncthreads();

    if (t < RPB * Dd) {
        const int r = t >> 6, c = t & 63;
        ysh[r][c] = hsh[r][c] + pshy[0][r][c] + pshy[1][r][c];
    }
    __syncthreads();

    // a/b: thread = (c:256, rpair:4)
    {
        const int c = t & 255;
        const int rp = t >> 8;
        const int rA = rp * 2, rB = rp * 2 + 1;
        const float bias = __ldg(b1 + c);
        float faA = 0.f, faB = 0.f, fbA = 0.f, fbB = 0.f;
#pragma unroll 8
        for (int d = 0; d < Dd; d++) {
            const float wa = __ldg(W1 + d * HIDD + c);
            const float wb = __ldg(W1 + (Dd + d) * HIDD + c);
            const float yA = ysh[rA][d], yB = ysh[rB][d];
            faA += yA * wa; faB += yB * wa;
            fbA += yA * wb; fbB += yB * wb;
        }
        ash[rA][c] = faA + bias;
        ash[rB][c] = faB + bias;
        g_bb[(row0 + rA) * HIDD + c] = fbA;
        g_bb[(row0 + rB) * HIDD + c] = fbB;
    }

    gsync();

    // ================= PHASE C: scatter =================
    {
        const int r = warp & 7;
        const int es = warp >> 3;
        const int i = n0 + r;
        const int cnt = csh[r];
        const int* jrow = jsh[r];
        const int h0 = lane * 8;

        const float4 a0 = *(const float4*)&ash[r][h0];
        const float4 a1 = *(const float4*)&ash[r][h0 + 4];
        float4 w[8];
#pragma unroll
        for (int k = 0; k < 8; k++) w[k] = __ldg((const float4*)W2 + h0 + k);
        const float b20 = __ldg(b2 + 0), b21 = __ldg(b2 + 1);
        const float b22 = __ldg(b2 + 2), b23 = __ldg(b2 + 3);

        for (int e = es; e < cnt; e += 4) {
            const int j = jrow[e];
            const float4* bp = (const float4*)(g_bb + ((size_t)(b * Nn + j)) * HIDD + h0);
            const float4 bv0 = bp[0], bv1 = bp[1];

            float acc0 = 0.f, acc1 = 0.f, acc2 = 0.f, acc3 = 0.f;
            float tt;
#define RELU_FMA(AV, BV, WK) \
            tt = fmaxf((AV) + (BV), 0.f); \
            acc0 += tt * (WK).x; acc1 += tt * (WK).y; acc2 += tt * (WK).z; acc3 += tt * (WK).w;
            RELU_FMA(a0.x, bv0.x, w[0]);
            RELU_FMA(a0.y, bv0.y, w[1]);
            RELU_FMA(a0.z, bv0.z, w[2]);
            RELU_FMA(a0.w, bv0.w, w[3]);
            RELU_FMA(a1.x, bv1.x, w[4]);
            RELU_FMA(a1.y, bv1.y, w[5]);
            RELU_FMA(a1.z, bv1.z, w[6]);
            RELU_FMA(a1.w, bv1.w, w[7]);
#undef RELU_FMA

#pragma unroll
            for (int o = 16; o > 0; o >>= 1) {
                acc0 += __shfl_xor_sync(0xffffffffu, acc0, o);
                acc1 += __shfl_xor_sync(0xffffffffu, acc1, o);
                acc2 += __shfl_xor_sync(0xffffffffu, acc2, o);
                acc3 += __shfl_xor_sync(0xffffffffu, acc3, o);
            }
            if (lane == 0) {
                out[(((size_t)(b * Cc + 0) * Nn + i) * Nn) + j] = acc0 + b20;
                out[(((size_t)(b * Cc + 1) * Nn + i) * Nn) + j] = acc1 + b21;
                out[(((size_t)(b * Cc + 2) * Nn + i) * Nn) + j] = acc2 + b22;
                out[(((size_t)(b * Cc + 3) * Nn + i) * Nn) + j] = acc3 + b23;
            }
        }
    }
}

// ---------------------------------------------------------------------------
extern "C" void kernel_launch(void* const* d_in, const int* in_sizes, int n_in,
                              void* d_out, int out_size) {
    const float* x     = (const float*)d_in[0];
    const float* adj   = (const float*)d_in[1];
    const float* W_emb = (const float*)d_in[2];
    const float* Wq    = (const float*)d_in[3];
    const float* Wk    = (const float*)d_in[4];
    const float* Wv    = (const float*)d_in[5];
    const float* Wo    = (const float*)d_in[6];
    const float* W1    = (const float*)d_in[7];
    const float* b1    = (const float*)d_in[8];
    const float* W2    = (const float*)d_in[9];
    const float* b2    = (const float*)d_in[10];
    float* out = (float*)d_out;

    fused_all<<<NB, 1024>>>(x, adj, W_emb, Wq, Wk, Wv, Wo, W1, b1, W2, b2, out);
}